// round 8
// baseline (speedup 1.0000x reference)
#include <cuda_runtime.h>

// PEquiNN: o_x = l_xx*X + (g_xx*rowsum(X) + g_yx*rowsum(Y)) per row
//          o_y = l_yy*Y + (g_yy*rowsum(Y) + g_xy*rowsum(X)) per row
// X, Y: [8192, 4096] f32. Single-pass streaming: 256 MiB read + 256 MiB write
// (provably minimal). Pinned at ~80% DRAM (r/w turnaround) across 4 cells.
//
// R7: two rows per CTA, one-shot grid (4096 CTAs x 512t). Persistent loop
// (R6) regressed -17% -- cross-CTA overlap is what hides the reduce barrier,
// so keep one-shot CTAs. This round doubles per-thread MLP (8 front-batched
// LDG.128) and halves barriers-per-byte: one __syncthreads serves both rows.
// Split-warp layout (warps 0-7 = X, 8-15 = Y), plain ld/st (hints hurt).

#define N_COLS 4096
#define VEC_PER_ROW (N_COLS / 4)       // 1024 float4 per row
#define THREADS 512
#define HALF 256                        // threads per matrix half
#define V_PER_THREAD (VEC_PER_ROW / HALF)  // 4 float4 per half-row per thread
#define ROWS_PER_CTA 2

__global__ __launch_bounds__(THREADS)
void peq_kernel(const float4* __restrict__ X,
                const float4* __restrict__ Y,
                const float* __restrict__ p_lxx,
                const float* __restrict__ p_lyy,
                const float* __restrict__ p_gxx,
                const float* __restrict__ p_gxy,
                const float* __restrict__ p_gyx,
                const float* __restrict__ p_gyy,
                float4* __restrict__ OX,
                float4* __restrict__ OY)
{
    const int tid = threadIdx.x;
    const int half_tid = tid & (HALF - 1);
    const bool is_y = tid >= HALF;

    const float4* __restrict__ SRC = is_y ? Y : X;
    float4* __restrict__ DST = is_y ? OY : OX;

    const size_t base0 = (size_t)(blockIdx.x * ROWS_PER_CTA)     * VEC_PER_ROW + half_tid;
    const size_t base1 = (size_t)(blockIdx.x * ROWS_PER_CTA + 1) * VEC_PER_ROW + half_tid;

    // Front-batch all 8 loads (two half-rows), then reduce both.
    float4 v0[V_PER_THREAD];
    float4 v1[V_PER_THREAD];
#pragma unroll
    for (int i = 0; i < V_PER_THREAD; i++) v0[i] = SRC[base0 + i * HALF];
#pragma unroll
    for (int i = 0; i < V_PER_THREAD; i++) v1[i] = SRC[base1 + i * HALF];

    float s0 = 0.f, s1 = 0.f;
#pragma unroll
    for (int i = 0; i < V_PER_THREAD; i++) {
        s0 += (v0[i].x + v0[i].y) + (v0[i].z + v0[i].w);
        s1 += (v1[i].x + v1[i].y) + (v1[i].z + v1[i].w);
    }

    // Warp reduce both row partials.
#pragma unroll
    for (int o = 16; o > 0; o >>= 1) {
        s0 += __shfl_xor_sync(0xFFFFFFFFu, s0, o);
        s1 += __shfl_xor_sync(0xFFFFFFFFu, s1, o);
    }

    // Cross-warp: 16 warps x 2 rows. Warps 0-7 hold X partials, 8-15 Y.
    __shared__ float ssum[2][THREADS / 32];
    const int wid = tid >> 5;
    if ((tid & 31) == 0) { ssum[0][wid] = s0; ssum[1][wid] = s1; }
    __syncthreads();

    float sx0 = 0.f, sy0 = 0.f, sx1 = 0.f, sy1 = 0.f;
#pragma unroll
    for (int i = 0; i < 8; i++) {
        sx0 += ssum[0][i];
        sx1 += ssum[1][i];
    }
#pragma unroll
    for (int i = 8; i < 16; i++) {
        sy0 += ssum[0][i];
        sy1 += ssum[1][i];
    }

    const float lxx = __ldg(p_lxx);
    const float lyy = __ldg(p_lyy);
    const float gxx = __ldg(p_gxx);
    const float gxy = __ldg(p_gxy);
    const float gyx = __ldg(p_gyx);
    const float gyy = __ldg(p_gyy);

    const float l  = is_y ? lyy : lxx;
    const float b0 = is_y ? (gyy * sy0 + gxy * sx0) : (gxx * sx0 + gyx * sy0);
    const float b1 = is_y ? (gyy * sy1 + gxy * sx1) : (gxx * sx1 + gyx * sy1);

#pragma unroll
    for (int i = 0; i < V_PER_THREAD; i++) {
        float4 o;
        o.x = fmaf(l, v0[i].x, b0);
        o.y = fmaf(l, v0[i].y, b0);
        o.z = fmaf(l, v0[i].z, b0);
        o.w = fmaf(l, v0[i].w, b0);
        DST[base0 + i * HALF] = o;
    }
#pragma unroll
    for (int i = 0; i < V_PER_THREAD; i++) {
        float4 o;
        o.x = fmaf(l, v1[i].x, b1);
        o.y = fmaf(l, v1[i].y, b1);
        o.z = fmaf(l, v1[i].z, b1);
        o.w = fmaf(l, v1[i].w, b1);
        DST[base1 + i * HALF] = o;
    }
}

extern "C" void kernel_launch(void* const* d_in, const int* in_sizes, int n_in,
                              void* d_out, int out_size)
{
    const float4* X = (const float4*)d_in[0];
    const float4* Y = (const float4*)d_in[1];
    const float* lxx = (const float*)d_in[2];
    const float* lyy = (const float*)d_in[3];
    const float* gxx = (const float*)d_in[4];
    const float* gxy = (const float*)d_in[5];
    const float* gyx = (const float*)d_in[6];
    const float* gyy = (const float*)d_in[7];

    const int total = in_sizes[0];          // R * N = 8192 * 4096
    const int rows = total / N_COLS;        // 8192

    float* out = (float*)d_out;
    float4* OX = (float4*)out;                          // o_x first
    float4* OY = (float4*)(out + (size_t)total);        // o_y second

    peq_kernel<<<rows / ROWS_PER_CTA, THREADS>>>(X, Y, lxx, lyy, gxx, gxy,
                                                 gyx, gyy, OX, OY);
}

// round 9
// speedup vs baseline: 1.1652x; 1.1652x over previous
#include <cuda_runtime.h>

// PEquiNN: o_x = l_xx*X + (g_xx*rowsum(X) + g_yx*rowsum(Y)) per row
//          o_y = l_yy*Y + (g_yy*rowsum(Y) + g_xy*rowsum(X)) per row
// X, Y: [8192, 4096] f32. Single-pass streaming: 256 MiB read + 256 MiB
// write (provably minimal traffic -- the theta matrices are l*I + g*ones,
// so the 4 "GEMMs" collapse to rowsum + axpy).
//
// FINAL (R2 reproduction, best measured cell of 7 benches):
//   - one-shot grid, one row per CTA (8192 CTAs): cross-CTA overlap hides
//     the reduce barrier (persistent loop: -10%; 2 rows/CTA: -17%).
//   - 512 threads split-warp: warps 0-7 hold the X row, 8-15 the Y row
//     (4 float4/thread -> 32 regs -> 90% occupancy).
//   - measured ceiling: ~6.3 TB/s = ~80% of HBM spec, the practical limit
//     for 1:1 read/write fp32 streaming on sm_103a.

#define N_COLS 4096
#define VEC_PER_ROW (N_COLS / 4)       // 1024 float4 per row
#define THREADS 512
#define HALF 256                        // threads per matrix half
#define V_PER_THREAD (VEC_PER_ROW / HALF)  // 4 float4 = 16 floats per thread

__global__ __launch_bounds__(THREADS)
void peq_kernel(const float4* __restrict__ X,
                const float4* __restrict__ Y,
                const float* __restrict__ p_lxx,
                const float* __restrict__ p_lyy,
                const float* __restrict__ p_gxx,
                const float* __restrict__ p_gxy,
                const float* __restrict__ p_gyx,
                const float* __restrict__ p_gyy,
                float4* __restrict__ OX,
                float4* __restrict__ OY)
{
    const int row = blockIdx.x;
    const size_t base = (size_t)row * VEC_PER_ROW;
    const int tid = threadIdx.x;
    const int half_tid = tid & (HALF - 1);   // 0..255 within the half
    const bool is_y = tid >= HALF;           // warps 8-15 handle Y

    const float4* __restrict__ SRC = is_y ? Y : X;

    // Load this half-row into registers; accumulate partial sum.
    float4 v[V_PER_THREAD];
    float s = 0.f;
#pragma unroll
    for (int i = 0; i < V_PER_THREAD; i++) {
        v[i] = __ldcs(&SRC[base + half_tid + i * HALF]);
        s += (v[i].x + v[i].y) + (v[i].z + v[i].w);
    }

    // Warp reduce.
#pragma unroll
    for (int o = 16; o > 0; o >>= 1)
        s += __shfl_xor_sync(0xFFFFFFFFu, s, o);

    // Cross-warp: warps 0-7 carry X partials, warps 8-15 carry Y partials.
    __shared__ float ssum[THREADS / 32];     // 16 entries
    const int wid = tid >> 5;
    if ((tid & 31) == 0) ssum[wid] = s;
    __syncthreads();

    float sx = 0.f, sy = 0.f;
#pragma unroll
    for (int i = 0; i < 8; i++)  sx += ssum[i];
#pragma unroll
    for (int i = 8; i < 16; i++) sy += ssum[i];

    const float lxx = __ldg(p_lxx);
    const float lyy = __ldg(p_lyy);
    const float gxx = __ldg(p_gxx);
    const float gxy = __ldg(p_gxy);
    const float gyx = __ldg(p_gyx);
    const float gyy = __ldg(p_gyy);

    // Per-half diagonal scale + broadcast term.
    const float l = is_y ? lyy : lxx;
    const float b = is_y ? (gyy * sy + gxy * sx)    // o_y broadcast
                         : (gxx * sx + gyx * sy);   // o_x broadcast

    float4* __restrict__ DST = is_y ? OY : OX;

#pragma unroll
    for (int i = 0; i < V_PER_THREAD; i++) {
        float4 o;
        o.x = fmaf(l, v[i].x, b);
        o.y = fmaf(l, v[i].y, b);
        o.z = fmaf(l, v[i].z, b);
        o.w = fmaf(l, v[i].w, b);
        __stcs(&DST[base + half_tid + i * HALF], o);
    }
}

extern "C" void kernel_launch(void* const* d_in, const int* in_sizes, int n_in,
                              void* d_out, int out_size)
{
    const float4* X = (const float4*)d_in[0];
    const float4* Y = (const float4*)d_in[1];
    const float* lxx = (const float*)d_in[2];
    const float* lyy = (const float*)d_in[3];
    const float* gxx = (const float*)d_in[4];
    const float* gxy = (const float*)d_in[5];
    const float* gyx = (const float*)d_in[6];
    const float* gyy = (const float*)d_in[7];

    const int total = in_sizes[0];          // R * N = 8192 * 4096
    const int rows = total / N_COLS;        // 8192

    float* out = (float*)d_out;
    float4* OX = (float4*)out;                          // o_x first
    float4* OY = (float4*)(out + (size_t)total);        // o_y second

    peq_kernel<<<rows, THREADS>>>(X, Y, lxx, lyy, gxx, gxy, gyx, gyy, OX, OY);
}